// round 7
// baseline (speedup 1.0000x reference)
#include <cuda_runtime.h>
#include <cuda_fp16.h>
#include <cstdint>
#include <math.h>

#define NMAX 262144
#define GMAX 8192
#define EDIM 118
#define FDIM 128
#define KTAB 512          // intervals per branch (KTAB+1 grid points)
#define WPITCH 129        // odd pitch -> conflict-free smem dot reads

// ---------------- scratch (device globals; no allocation) ----------------
__device__ float   g_y[NMAX];
__device__ float   g_denom[GMAX];
__device__ float   g_dot[EDIM * 2];
__device__ float   g_amax;
__device__ float   g_lin[2 * FDIM];                  // F'(0) per branch
__device__ float   g_tab[2][KTAB + 1][FDIM];         // residual G(|att|), fp32
__device__ __half2 g_pair[2][KTAB + 1][FDIM];        // (G[j], G[j+1]) fp16 pairs

// ---------------- helpers ----------------
__device__ __forceinline__ float s1f(float x) {      // silu(x) - x/2, O(x^2), no cancellation
    return 0.5f * x * tanhf(0.5f * x);
}

// ---------------- kernel: zero denom + amax + dot table ----------------
__global__ void k_prep(const float* __restrict__ Wq, const float* __restrict__ Wk,
                       const float* __restrict__ psi, int G) {
    __shared__ float sk[256];
    __shared__ float smax[8];
    int t = threadIdx.x;
    for (int i = t; i < G; i += 256) g_denom[i] = 0.f;
    sk[t] = Wk[t];
    float m = 0.f;
    for (int i = t; i < G; i += 256) m = fmaxf(m, fabsf(psi[i]));
#pragma unroll
    for (int o = 16; o; o >>= 1) m = fmaxf(m, __shfl_xor_sync(0xffffffffu, m, o));
    if ((t & 31) == 0) smax[t >> 5] = m;
    __syncthreads();
    if (t == 0) {
        float mm = 1e-12f;
        for (int i = 0; i < 8; ++i) mm = fmaxf(mm, smax[i]);
        g_amax = mm;
    }
    if (t < EDIM) {
        float a0 = 0.f, a1 = 0.f;
#pragma unroll 8
        for (int f = 0; f < FDIM; ++f) {
            float w = Wq[f * EDIM + t];
            a0 = fmaf(w, sk[f], a0);
            a1 = fmaf(w, sk[FDIM + f], a1);
        }
        g_dot[t * 2 + 0] = a0;
        g_dot[t * 2 + 1] = a1;
    }
}

// ---------------- kernel: flat streaming nonzero scan -> y, denom -------------
// One-hot matrix scanned as flat float4 stream; the single nonzero per row
// identifies (atom, element) via constant division.
__global__ void __launch_bounds__(256)
k_scan(const float4* __restrict__ oh4, const float* __restrict__ psi,
       const int* __restrict__ bs, int nvec) {
    int i = blockIdx.x * blockDim.x + threadIdx.x;
    if (i >= nvec) return;
    float4 v = __ldcs(oh4 + i);
    float vv[4] = {v.x, v.y, v.z, v.w};
#pragma unroll
    for (int c = 0; c < 4; ++c) {
        if (vv[c] != 0.f) {
            unsigned f = 4u * (unsigned)i + (unsigned)c;
            unsigned atom = f / 118u;
            unsigned e = f - atom * 118u;
            int g = bs[atom];
            float p = psi[g];
            int r = (p < 0.f) ? 1 : 0;
            float qk = g_dot[e * 2 + r] * 0.08838834764831845f;  // 1/sqrt(128)
            float y = (qk > 20.f) ? qk : log1pf(expf(qk));
            g_y[atom] = y;
            atomicAdd(&g_denom[g], y);
        }
    }
}

// ---------------- kernel: build residual table + F'(0), all fp32 --------------
//   hlin = W1@wv;  h(a) = 0.5a*hlin + W1@s1(a*wv)
//   F(a) - a*F1 = W2 @ [ 0.5*(W1@s1(a*wv)) + s1(h(a)) ]
//   F1 = wv + 0.25*(W2@hlin)
// grid: 258 blocks = 2 branches x 129 groups of 4 nodes; 128 threads
__global__ void k_tab(const float* __restrict__ Wv, const float* __restrict__ W1,
                      const float* __restrict__ W2) {
    extern __shared__ float sm[];
    float* sW1 = sm;                       // [128][WPITCH]
    float* sW2 = sW1 + FDIM * WPITCH;      // [128][WPITCH]
    float* swv = sW2 + FDIM * WPITCH;      // [128]
    float* shl = swv + FDIM;               // [128] hlin
    float* ssv = shl + FDIM;               // [128] s1(a*wv)
    float* sbr = ssv + FDIM;               // [128] bracket
    int t = threadIdx.x;
    int b = blockIdx.x;
    int r = (b >= 129) ? 1 : 0;
    int i0 = (b - r * 129) * 4;
    float sgn = r ? -1.f : 1.f;

    const float4* W1v = (const float4*)W1;
    const float4* W2v = (const float4*)W2;
    for (int i = t; i < FDIM * 32; i += 128) {
        int row = i >> 5, c = (i & 31) * 4;
        float4 v1 = W1v[i];
        float* p = sW1 + row * WPITCH + c;
        p[0] = v1.x; p[1] = v1.y; p[2] = v1.z; p[3] = v1.w;
        float4 v2 = W2v[i];
        float* q = sW2 + row * WPITCH + c;
        q[0] = v2.x; q[1] = v2.y; q[2] = v2.z; q[3] = v2.w;
    }
    float wv = Wv[r * FDIM + t];
    swv[t] = wv;
    __syncthreads();

    const float* w1row = sW1 + t * WPITCH;
    const float* w2row = sW2 + t * WPITCH;
    {
        float d0 = 0.f, d1 = 0.f, d2 = 0.f, d3 = 0.f;
#pragma unroll
        for (int k = 0; k < FDIM; k += 4) {
            d0 = fmaf(w1row[k],     swv[k],     d0);
            d1 = fmaf(w1row[k + 1], swv[k + 1], d1);
            d2 = fmaf(w1row[k + 2], swv[k + 2], d2);
            d3 = fmaf(w1row[k + 3], swv[k + 3], d3);
        }
        shl[t] = (d0 + d1) + (d2 + d3);
    }
    __syncthreads();
    float hlin = shl[t];

    if (i0 == 0) {  // F1 = wv + 0.25*(W2@hlin)
        float d0 = 0.f, d1 = 0.f, d2 = 0.f, d3 = 0.f;
#pragma unroll
        for (int k = 0; k < FDIM; k += 4) {
            d0 = fmaf(w2row[k],     shl[k],     d0);
            d1 = fmaf(w2row[k + 1], shl[k + 1], d1);
            d2 = fmaf(w2row[k + 2], shl[k + 2], d2);
            d3 = fmaf(w2row[k + 3], shl[k + 3], d3);
        }
        g_lin[r * FDIM + t] = fmaf(0.25f, (d0 + d1) + (d2 + d3), wv);
    }

    float amax = g_amax;
    for (int i = i0; i < i0 + 4 && i <= KTAB; ++i) {
        float mag = (i == 0) ? (amax * (1.f / 4096.f)) : (amax * (float)i * (1.f / KTAB));
        float a = sgn * mag;
        ssv[t] = s1f(a * wv);
        __syncthreads();
        float d0 = 0.f, d1 = 0.f, d2 = 0.f, d3 = 0.f;
#pragma unroll
        for (int k = 0; k < FDIM; k += 4) {
            d0 = fmaf(w1row[k],     ssv[k],     d0);
            d1 = fmaf(w1row[k + 1], ssv[k + 1], d1);
            d2 = fmaf(w1row[k + 2], ssv[k + 2], d2);
            d3 = fmaf(w1row[k + 3], ssv[k + 3], d3);
        }
        float tt = (d0 + d1) + (d2 + d3);          // W1@s1(a*wv)
        float h = fmaf(0.5f * a, hlin, tt);
        sbr[t] = fmaf(0.5f, tt, s1f(h));
        __syncthreads();
        float e0 = 0.f, e1 = 0.f, e2 = 0.f, e3 = 0.f;
#pragma unroll
        for (int k = 0; k < FDIM; k += 4) {
            e0 = fmaf(w2row[k],     sbr[k],     e0);
            e1 = fmaf(w2row[k + 1], sbr[k + 1], e1);
            e2 = fmaf(w2row[k + 2], sbr[k + 2], e2);
            e3 = fmaf(w2row[k + 3], sbr[k + 3], e3);
        }
        float resid = (e0 + e1) + (e2 + e3);
        g_tab[r][i][t] = resid / (a * a);
        __syncthreads();
    }
}

// ---------------- kernel: pack fp32 table -> fp16 endpoint pairs --------------
__global__ void k_pack() {
    int id = blockIdx.x * blockDim.x + threadIdx.x;   // 2*(KTAB+1)*128
    int total = 2 * (KTAB + 1) * FDIM;
    if (id >= total) return;
    int f = id & 127;
    int j = (id >> 7) % (KTAB + 1);
    int r = id / ((KTAB + 1) * FDIM);
    int j1 = (j < KTAB) ? j + 1 : KTAB;
    g_pair[r][j][f] = __floats2half2_rn(g_tab[r][j][f], g_tab[r][j1][f]);
}

// ---------------- kernel: per-atom single-load lerp + linear epilogue ---------
__global__ void __launch_bounds__(256)
k_out(const float* __restrict__ psi, const int* __restrict__ bs,
      float* __restrict__ out, int N) {
    __shared__ float sF1[2 * FDIM];
    int tid = threadIdx.x;
    sF1[tid] = g_lin[tid];
    __syncthreads();
    int n = blockIdx.x * 8 + (tid >> 5);
    if (n >= N) return;
    int lane = tid & 31;
    int g = bs[n];
    float p = psi[g];
    float att = p * g_y[n] / (g_denom[g] + 1e-6f);
    int r = (p < 0.f) ? 1 : 0;
    float x = fabsf(att) * ((float)KTAB / g_amax);
    int j = (int)x;
    if (j > KTAB - 1) j = KTAB - 1;
    float w = x - (float)j;
    const float4* rowp = (const float4*)&g_pair[r][j][0];
    float4 raw = __ldg(rowp + lane);          // 4 half2 pairs = features 4*lane..+3
    const __half2* hp = (const __half2*)&raw;
    float4 f1 = ((const float4*)(sF1 + r * FDIM))[lane];
    float att2 = att * att;
    float2 q0 = __half22float2(hp[0]);
    float2 q1 = __half22float2(hp[1]);
    float2 q2 = __half22float2(hp[2]);
    float2 q3 = __half22float2(hp[3]);
    float4 o;
    o.x = fmaf(att, f1.x, att2 * fmaf(w, q0.y - q0.x, q0.x));
    o.y = fmaf(att, f1.y, att2 * fmaf(w, q1.y - q1.x, q1.x));
    o.z = fmaf(att, f1.z, att2 * fmaf(w, q2.y - q2.x, q2.x));
    o.w = fmaf(att, f1.w, att2 * fmaf(w, q3.y - q3.x, q3.x));
    ((float4*)out)[(size_t)n * 32 + lane] = o;
}

// ---------------- launch ----------------
extern "C" void kernel_launch(void* const* d_in, const int* in_sizes, int n_in,
                              void* d_out, int out_size) {
    const float* oh  = (const float*)d_in[0];
    const float* psi = (const float*)d_in[1];
    const float* Wq  = (const float*)d_in[2];
    const float* Wk  = (const float*)d_in[3];
    const float* Wv  = (const float*)d_in[4];
    const float* W1  = (const float*)d_in[5];
    const float* W2  = (const float*)d_in[6];
    const int*   bs  = (const int*)d_in[7];
    int N = in_sizes[7];
    int G = in_sizes[1];
    float* out = (float*)d_out;

    const int tab_smem = (2 * FDIM * WPITCH + 4 * FDIM) * 4;   // ~134 KB
    cudaFuncSetAttribute(k_tab, cudaFuncAttributeMaxDynamicSharedMemorySize, tab_smem);

    int nvec = (N * EDIM) / 4;                // N*118 divisible by 4
    int ptotal = 2 * (KTAB + 1) * FDIM;

    k_prep<<<1, 256>>>(Wq, Wk, psi, G);
    k_scan<<<(nvec + 255) / 256, 256>>>((const float4*)oh, psi, bs, nvec);
    k_tab<<<258, 128, tab_smem>>>(Wv, W1, W2);
    k_pack<<<(ptotal + 255) / 256, 256>>>();
    k_out<<<(N + 7) / 8, 256>>>(psi, bs, out, N);
}

// round 8
// speedup vs baseline: 1.4570x; 1.4570x over previous
#include <cuda_runtime.h>
#include <cuda_fp16.h>
#include <cstdint>
#include <math.h>

#define NMAX 262144
#define GMAX 8192
#define EDIM 118
#define FDIM 128
#define KTAB 1024         // intervals per branch (KTAB+1 grid rows)
#define WPITCH 129        // odd pitch -> conflict-free smem dot reads

// ---------------- scratch (device globals; no allocation) ----------------
__device__ float  g_y[NMAX];
__device__ float  g_att[NMAX];
__device__ float  g_denom[GMAX];
__device__ float  g_dot[EDIM * 2];
__device__ float  g_amax;
__device__ float  g_lin[2 * FDIM];                   // F'(0) per branch
__device__ __half g_tabh[2][KTAB + 1][FDIM];         // residual G(|att|), fp16 rows (256B)

// ---------------- helpers ----------------
__device__ __forceinline__ float s1f(float x) {      // silu(x) - x/2, O(x^2), no cancellation
    return 0.5f * x * tanhf(0.5f * x);
}

// ---------------- kernel: zero denom + amax + dot table ----------------
__global__ void k_prep(const float* __restrict__ Wq, const float* __restrict__ Wk,
                       const float* __restrict__ psi, int G) {
    __shared__ float sk[256];
    __shared__ float smax[8];
    int t = threadIdx.x;
    for (int i = t; i < G; i += 256) g_denom[i] = 0.f;
    sk[t] = Wk[t];
    float m = 0.f;
    for (int i = t; i < G; i += 256) m = fmaxf(m, fabsf(psi[i]));
#pragma unroll
    for (int o = 16; o; o >>= 1) m = fmaxf(m, __shfl_xor_sync(0xffffffffu, m, o));
    if ((t & 31) == 0) smax[t >> 5] = m;
    __syncthreads();
    if (t == 0) {
        float mm = 1e-12f;
        for (int i = 0; i < 8; ++i) mm = fmaxf(mm, smax[i]);
        g_amax = mm;
    }
    if (t < EDIM) {
        float a0 = 0.f, a1 = 0.f;
#pragma unroll 8
        for (int f = 0; f < FDIM; ++f) {
            float w = Wq[f * EDIM + t];
            a0 = fmaf(w, sk[f], a0);
            a1 = fmaf(w, sk[FDIM + f], a1);
        }
        g_dot[t * 2 + 0] = a0;
        g_dot[t * 2 + 1] = a1;
    }
}

// ---------------- kernel: grid-stride flat scan (4x float4 ILP) ---------------
__global__ void __launch_bounds__(512)
k_scan(const float4* __restrict__ oh4, const float* __restrict__ psi,
       const int* __restrict__ bs, int nvec) {
    int stride = gridDim.x * blockDim.x;
    for (int base = blockIdx.x * blockDim.x + threadIdx.x; base < nvec; base += 4 * stride) {
        float4 v[4];
        int ii[4];
#pragma unroll
        for (int u = 0; u < 4; ++u) {
            ii[u] = base + u * stride;
            if (ii[u] < nvec) v[u] = __ldcs(oh4 + ii[u]);
            else v[u] = make_float4(0.f, 0.f, 0.f, 0.f);
        }
#pragma unroll
        for (int u = 0; u < 4; ++u) {
            float vv[4] = {v[u].x, v[u].y, v[u].z, v[u].w};
#pragma unroll
            for (int c = 0; c < 4; ++c) {
                if (vv[c] != 0.f) {
                    unsigned f = 4u * (unsigned)ii[u] + (unsigned)c;
                    unsigned atom = f / 118u;
                    unsigned e = f - atom * 118u;
                    int g = bs[atom];
                    float p = psi[g];
                    int r = (p < 0.f) ? 1 : 0;
                    float qk = g_dot[e * 2 + r] * 0.08838834764831845f;  // 1/sqrt(128)
                    float y = (qk > 20.f) ? qk : log1pf(expf(qk));
                    g_y[atom] = y;
                    atomicAdd(&g_denom[g], y);
                }
            }
        }
    }
}

// ---------------- kernel: two-phase residual table + F'(0) --------------------
//   hlin = W1@wv;  h(a) = 0.5a*hlin + W1@s1(a*wv)
//   F(a) - a*F1 = W2 @ [ 0.5*(W1@s1(a*wv)) + s1(h(a)) ]
//   F1 = wv + 0.25*(W2@hlin)
// grid: 258 blocks = 2 branches x 129 groups of 8 nodes; 128 threads
__global__ void k_tab(const float* __restrict__ Wv, const float* __restrict__ W1,
                      const float* __restrict__ W2) {
    extern __shared__ float sm[];
    float* sW  = sm;                       // [128][WPITCH] (W1, then W2)
    float* swv = sW + FDIM * WPITCH;       // [128]
    float* shl = swv + FDIM;               // [128] hlin
    float* sSv = shl + FDIM;               // [8][128] s1(a_u*wv)
    float* sB  = sSv + 8 * FDIM;           // [8][128] bracket
    int t = threadIdx.x;
    int b = blockIdx.x;
    int r = (b >= 129) ? 1 : 0;
    int i0 = (b - r * 129) * 8;
    float sgn = r ? -1.f : 1.f;

    const float4* W1v = (const float4*)W1;
    for (int i = t; i < FDIM * 32; i += 128) {
        int row = i >> 5, c = (i & 31) * 4;
        float4 v = W1v[i];
        float* p = sW + row * WPITCH + c;
        p[0] = v.x; p[1] = v.y; p[2] = v.z; p[3] = v.w;
    }
    float wv = Wv[r * FDIM + t];
    swv[t] = wv;
    __syncthreads();

    const float* wrow = sW + t * WPITCH;
    float hlin;
    {
        float d0 = 0.f, d1 = 0.f, d2 = 0.f, d3 = 0.f;
#pragma unroll
        for (int k = 0; k < FDIM; k += 4) {
            d0 = fmaf(wrow[k],     swv[k],     d0);
            d1 = fmaf(wrow[k + 1], swv[k + 1], d1);
            d2 = fmaf(wrow[k + 2], swv[k + 2], d2);
            d3 = fmaf(wrow[k + 3], swv[k + 3], d3);
        }
        hlin = (d0 + d1) + (d2 + d3);
        shl[t] = hlin;
    }
    float amax = g_amax;
    float av[8];
#pragma unroll
    for (int u = 0; u < 8; ++u) {
        int i = i0 + u;
        float mag = (i == 0) ? (amax * (1.f / 8192.f)) : (amax * (float)i * (1.f / KTAB));
        av[u] = sgn * mag;
        sSv[u * FDIM + t] = s1f(av[u] * wv);
    }
    __syncthreads();

    for (int u = 0; u < 8; ++u) {
        if (i0 + u > KTAB) break;
        const float* sv = sSv + u * FDIM;
        float d0 = 0.f, d1 = 0.f, d2 = 0.f, d3 = 0.f;
#pragma unroll
        for (int k = 0; k < FDIM; k += 4) {
            d0 = fmaf(wrow[k],     sv[k],     d0);
            d1 = fmaf(wrow[k + 1], sv[k + 1], d1);
            d2 = fmaf(wrow[k + 2], sv[k + 2], d2);
            d3 = fmaf(wrow[k + 3], sv[k + 3], d3);
        }
        float tt = (d0 + d1) + (d2 + d3);
        float h = fmaf(0.5f * av[u], hlin, tt);
        sB[u * FDIM + t] = fmaf(0.5f, tt, s1f(h));
    }
    __syncthreads();

    const float4* W2v = (const float4*)W2;
    for (int i = t; i < FDIM * 32; i += 128) {
        int row = i >> 5, c = (i & 31) * 4;
        float4 v = W2v[i];
        float* p = sW + row * WPITCH + c;
        p[0] = v.x; p[1] = v.y; p[2] = v.z; p[3] = v.w;
    }
    __syncthreads();

    if (i0 == 0) {
        float d0 = 0.f, d1 = 0.f, d2 = 0.f, d3 = 0.f;
#pragma unroll
        for (int k = 0; k < FDIM; k += 4) {
            d0 = fmaf(wrow[k],     shl[k],     d0);
            d1 = fmaf(wrow[k + 1], shl[k + 1], d1);
            d2 = fmaf(wrow[k + 2], shl[k + 2], d2);
            d3 = fmaf(wrow[k + 3], shl[k + 3], d3);
        }
        g_lin[r * FDIM + t] = fmaf(0.25f, (d0 + d1) + (d2 + d3), wv);
    }
    for (int u = 0; u < 8; ++u) {
        int i = i0 + u;
        if (i > KTAB) break;
        const float* bv = sB + u * FDIM;
        float e0 = 0.f, e1 = 0.f, e2 = 0.f, e3 = 0.f;
#pragma unroll
        for (int k = 0; k < FDIM; k += 4) {
            e0 = fmaf(wrow[k],     bv[k],     e0);
            e1 = fmaf(wrow[k + 1], bv[k + 1], e1);
            e2 = fmaf(wrow[k + 2], bv[k + 2], e2);
            e3 = fmaf(wrow[k + 3], bv[k + 3], e3);
        }
        float resid = (e0 + e1) + (e2 + e3);
        g_tabh[r][i][t] = __float2half(resid / (av[u] * av[u]));
    }
}

// ---------------- kernel: per-atom attention scalar ---------------------------
__global__ void __launch_bounds__(256)
k_att(const float* __restrict__ psi, const int* __restrict__ bs, int N) {
    int n = blockIdx.x * blockDim.x + threadIdx.x;
    if (n >= N) return;
    int g = bs[n];
    float p = psi[g];
    g_att[n] = p * g_y[n] / (g_denom[g] + 1e-6f);
}

// ---------------- kernel: table lookup + linear epilogue ----------------------
__global__ void __launch_bounds__(256)
k_out(float* __restrict__ out, int N) {
    __shared__ float sF1[2 * FDIM];
    __shared__ float s_scale;
    int tid = threadIdx.x;
    sF1[tid] = g_lin[tid];
    if (tid == 0) s_scale = (float)KTAB / g_amax;
    __syncthreads();
    int n = blockIdx.x * 8 + (tid >> 5);
    if (n >= N) return;
    int lane = tid & 31;
    float att = g_att[n];
    int r = (att < 0.f) ? 1 : 0;
    float x = fabsf(att) * s_scale;
    int j = __float2int_rn(x);
    if (j > KTAB) j = KTAB;
    const uint2* rowp = (const uint2*)(&g_tabh[r][j][0]);
    uint2 raw = __ldg(rowp + lane);            // 4 halves = features 4*lane..+3
    float2 g01 = __half22float2(*(const __half2*)&raw.x);
    float2 g23 = __half22float2(*(const __half2*)&raw.y);
    float4 f1 = ((const float4*)(sF1 + r * FDIM))[lane];
    float att2 = att * att;
    float4 o;
    o.x = fmaf(att, f1.x, att2 * g01.x);
    o.y = fmaf(att, f1.y, att2 * g01.y);
    o.z = fmaf(att, f1.z, att2 * g23.x);
    o.w = fmaf(att, f1.w, att2 * g23.y);
    __stcs((float4*)out + (size_t)n * 32 + lane, o);
}

// ---------------- launch ----------------
extern "C" void kernel_launch(void* const* d_in, const int* in_sizes, int n_in,
                              void* d_out, int out_size) {
    const float* oh  = (const float*)d_in[0];
    const float* psi = (const float*)d_in[1];
    const float* Wq  = (const float*)d_in[2];
    const float* Wk  = (const float*)d_in[3];
    const float* Wv  = (const float*)d_in[4];
    const float* W1  = (const float*)d_in[5];
    const float* W2  = (const float*)d_in[6];
    const int*   bs  = (const int*)d_in[7];
    int N = in_sizes[7];
    int G = in_sizes[1];
    float* out = (float*)d_out;

    const int tab_smem = (FDIM * WPITCH + 2 * FDIM + 16 * FDIM) * 4;   // ~75 KB
    cudaFuncSetAttribute(k_tab, cudaFuncAttributeMaxDynamicSharedMemorySize, tab_smem);

    int nvec = (N * EDIM) / 4;                // N*118 divisible by 4

    k_prep<<<1, 256>>>(Wq, Wk, psi, G);
    k_scan<<<592, 512>>>((const float4*)oh, psi, bs, nvec);
    k_tab<<<258, 128, tab_smem>>>(Wv, W1, W2);
    k_att<<<(N + 255) / 256, 256>>>(psi, bs, N);
    k_out<<<(N + 7) / 8, 256>>>(out, N);
}